// round 15
// baseline (speedup 1.0000x reference)
#include <cuda_runtime.h>
#include <math.h>
#include <float.h>

#define DDEPTH 7
#define IND   128
#define GRIDN 128
#define HIDN  256
#define BATCHN 2048
#define NT    129          // t in 0..128
#define TROW  512          // floats per (d,i) across all h

// k_main tiling: 2 batch-chunks (halved staging multiplicity)
#define MAIN_TPB 512
#define BCB   1024         // batches per CTA
#define IPC   16           // i's per CTA
#define NIC   8            // i-chunk count (128/IPC)
#define CHUNKF 64          // floats per t-row within one 32-h chunk
#define STAGE_N (NT * 16)               // 2064 float4 per buffer
#define STAGE_BYTES (NT * CHUNKF * 4)   // 33024
#define SMEM_MAIN (2 * STAGE_N * 16 + IPC * BCB * 4 + 64)   // 131648

// ---------------- scratch (static device memory; no allocation) ----------------
__device__ float g_xmin[IND];
__device__ float g_xmax[IND];
__device__ float g_Zt[IND * BATCHN];             // z transposed: [i][b]
__device__ float g_sg[DDEPTH * IND * GRIDN];     // sorted grids
__device__ int   g_perm[DDEPTH * IND * GRIDN];   // permutation
// layout: [d][i][hc8][t][64 floats]  (c_d folded in)
__device__ float g_T[(size_t)DDEPTH * IND * NT * TROW];
__device__ unsigned char g_tmap[(size_t)DDEPTH * IND * BATCHN];
__device__ float g_Hp[(size_t)NIC * BATCHN * HIDN];       // i-split partials
__device__ float g_Ha[BATCHN * HIDN];
__device__ float g_Hb[BATCHN * HIDN];
__device__ double g_sum[HIDN];
__device__ double g_sumsq[HIDN];
__device__ float2 g_bnp[HIDN];

// ---------------- mbarrier + bulk-copy helpers ----------------
__device__ __forceinline__ unsigned int smem_u32(const void* p) {
    return (unsigned int)__cvta_generic_to_shared(p);
}
__device__ __forceinline__ void mbar_init(unsigned int a, unsigned int cnt) {
    asm volatile("mbarrier.init.shared.b64 [%0], %1;" :: "r"(a), "r"(cnt) : "memory");
}
__device__ __forceinline__ void mbar_expect(unsigned int a, unsigned int tx) {
    asm volatile("mbarrier.arrive.expect_tx.shared.b64 _, [%0], %1;" :: "r"(a), "r"(tx) : "memory");
}
__device__ __forceinline__ void mbar_arrive(unsigned int a) {
    asm volatile("mbarrier.arrive.release.cta.shared.b64 _, [%0];" :: "r"(a) : "memory");
}
__device__ __forceinline__ void bulk_g2s(unsigned int dst, const void* src,
                                         unsigned int bytes, unsigned int mbar) {
    asm volatile("cp.async.bulk.shared::cta.global.mbarrier::complete_tx::bytes [%0], [%1], %2, [%3];"
                 :: "r"(dst), "l"(src), "r"(bytes), "r"(mbar) : "memory");
}
__device__ __forceinline__ void mbar_wait(unsigned int a, unsigned int parity) {
    asm volatile(
        "{\n\t"
        ".reg .pred P;\n\t"
        "W_%=:\n\t"
        "mbarrier.try_wait.parity.acquire.cta.shared::cta.b64 P, [%0], %1;\n\t"
        "@P bra D_%=;\n\t"
        "bra W_%=;\n\t"
        "D_%=:\n\t"
        "}"
        :: "r"(a), "r"(parity) : "memory");
}

// ---------------- 1. per-feature min/max over batch ----------------
__global__ void k_minmax(const float* __restrict__ x) {
    int i = blockIdx.x;
    float mn = FLT_MAX, mx = -FLT_MAX;
    for (int b = threadIdx.x; b < BATCHN; b += blockDim.x) {
        float v = x[b * IND + i];
        mn = fminf(mn, v);
        mx = fmaxf(mx, v);
    }
    __shared__ float smn[256], smx[256];
    smn[threadIdx.x] = mn; smx[threadIdx.x] = mx;
    __syncthreads();
    for (int s = 128; s > 0; s >>= 1) {
        if (threadIdx.x < s) {
            smn[threadIdx.x] = fminf(smn[threadIdx.x], smn[threadIdx.x + s]);
            smx[threadIdx.x] = fmaxf(smx[threadIdx.x], smx[threadIdx.x + s]);
        }
        __syncthreads();
    }
    if (threadIdx.x == 0) { g_xmin[i] = smn[0]; g_xmax[i] = smx[0]; }
}

// ---------------- 2. z transposed: g_Zt[i][b] ----------------
__global__ void k_z(const float* __restrict__ x) {
    int idx = blockIdx.x * blockDim.x + threadIdx.x;
    if (idx < BATCHN * IND) {
        int i = idx & (IND - 1);
        int b = idx >> 7;
        g_Zt[i * BATCHN + b] = (x[idx] - g_xmin[i]) / (g_xmax[i] - g_xmin[i] + 1e-6f);
    }
}

// ---------------- 3. sort grids per (d,i) via rank ----------------
__global__ void k_sort(const float* __restrict__ grids) {
    int di = blockIdx.x;
    int t  = threadIdx.x;
    __shared__ float sg[GRIDN];
    float g = grids[di * GRIDN + t];
    sg[t] = g;
    __syncthreads();
    int r = 0;
    #pragma unroll 8
    for (int j = 0; j < GRIDN; j++) {
        float gj = sg[j];
        r += (gj < g) || (gj == g && j < t);
    }
    g_sg[di * GRIDN + r]   = g;
    g_perm[di * GRIDN + r] = t;
}

// ---------------- 4. prefix tables with c_d folded; 32-h chunked layout ----------------
// 128 threads, each owns h pair (2*h2, 2*h2+1): float2 loads, float4 stores.
__global__ void __launch_bounds__(128) k_table(const float* __restrict__ fs,
                                               const float* __restrict__ ds) {
    __shared__ float ssg[GRIDN];
    __shared__ int   spm[GRIDN];
    int di = blockIdx.x;
    int d  = di >> 7;
    int h2 = threadIdx.x;               // 0..127
    ssg[h2] = g_sg[di * GRIDN + h2];
    spm[h2] = g_perm[di * GRIDN + h2];

    float w[DDEPTH], m = -FLT_MAX;
    for (int k = 0; k < DDEPTH; k++) m = fmaxf(m, ds[k]);
    float ssum = 0.f;
    for (int k = 0; k < DDEPTH; k++) { w[k] = expf(ds[k] - m); ssum += w[k]; }
    float cd = 0.f;
    for (int k = DDEPTH - 1; k >= d; --k) cd += w[k] / ssum;
    __syncthreads();

    const float* fbase = fs + (size_t)di * GRIDN * HIDN + 2 * h2;
    // chunk hc = h2>>4 (16 h-pairs per chunk); float offset in 64-float row = (h2&15)*4
    float* base = g_T + (size_t)di * NT * TROW + (h2 >> 4) * (NT * CHUNKF) + (h2 & 15) * 4;
    float a10 = 0.f, a20 = 0.f, a11 = 0.f, a21 = 0.f;
    *(float4*)base = make_float4(0.f, 0.f, 0.f, 0.f);
    for (int t0 = 0; t0 < GRIDN; t0 += 4) {
        int p0 = spm[t0 + 0], p1 = spm[t0 + 1], p2 = spm[t0 + 2], p3 = spm[t0 + 3];
        float2 f0 = *(const float2*)(fbase + p0 * HIDN);
        float2 f1 = *(const float2*)(fbase + p1 * HIDN);
        float2 f2 = *(const float2*)(fbase + p2 * HIDN);
        float2 f3 = *(const float2*)(fbase + p3 * HIDN);
        float g0 = ssg[t0 + 0], g1 = ssg[t0 + 1], g2 = ssg[t0 + 2], g3 = ssg[t0 + 3];
        a10 += f0.x; a20 = fmaf(g0, f0.x, a20);
        a11 += f0.y; a21 = fmaf(g0, f0.y, a21);
        *(float4*)(base + (size_t)(t0 + 1) * CHUNKF) = make_float4(cd*a10, cd*a20, cd*a11, cd*a21);
        a10 += f1.x; a20 = fmaf(g1, f1.x, a20);
        a11 += f1.y; a21 = fmaf(g1, f1.y, a21);
        *(float4*)(base + (size_t)(t0 + 2) * CHUNKF) = make_float4(cd*a10, cd*a20, cd*a11, cd*a21);
        a10 += f2.x; a20 = fmaf(g2, f2.x, a20);
        a11 += f2.y; a21 = fmaf(g2, f2.y, a21);
        *(float4*)(base + (size_t)(t0 + 3) * CHUNKF) = make_float4(cd*a10, cd*a20, cd*a11, cd*a21);
        a10 += f3.x; a20 = fmaf(g3, f3.x, a20);
        a11 += f3.y; a21 = fmaf(g3, f3.y, a21);
        *(float4*)(base + (size_t)(t0 + 4) * CHUNKF) = make_float4(cd*a10, cd*a20, cd*a11, cd*a21);
    }
}

// ---------------- 5. t[d,i,b] = #{ g < z } ----------------
__global__ void k_tmap() {
    int di = blockIdx.x;
    __shared__ float sg[GRIDN];
    if (threadIdx.x < GRIDN) sg[threadIdx.x] = g_sg[di * GRIDN + threadIdx.x];
    __syncthreads();
    int i = di & (IND - 1);
    for (int b = threadIdx.x; b < BATCHN; b += blockDim.x) {
        float z = g_Zt[i * BATCHN + b];
        int t = 0;
        #pragma unroll
        for (int s = 64; s > 0; s >>= 1) {
            int nt = t + s;
            if (nt <= GRIDN && sg[nt - 1] < z) t = nt;
        }
        g_tmap[(size_t)di * BATCHN + b] = (unsigned char)t;
    }
}

// ---------------- 6. main kernel: 1024-b CTAs, barrier-free mbarrier ring ----------------
// grid = 128: bc = x&1 (1024 b), hc = (x>>1)&7 (32 h), ic = x>>4 (8 chunks of 16 i).
// 512 threads (16 warps): hp = tid&15 (h-pair in chunk), bg = tid>>4 (32 batches each).
// Ring: full[k] (count 1 + expect_tx), empty[k] (count 16, per-warp lane0 arrive).
__global__ void __launch_bounds__(MAIN_TPB, 1) k_main() {
    extern __shared__ float4 dynsmem[];
    float4* bufs = dynsmem;                               // [2][STAGE_N]
    float*  z_s  = (float*)(dynsmem + 2 * STAGE_N);       // [IPC][BCB] 64KB
    unsigned long long* mbar = (unsigned long long*)(z_s + IPC * BCB);  // fb0,fb1,eb0,eb1

    int bc = blockIdx.x & 1;
    int hc = (blockIdx.x >> 1) & 7;
    int ic = blockIdx.x >> 4;
    int tid = threadIdx.x;
    int hp = tid & 15;
    int bg = tid >> 4;          // 0..31
    int b0 = bc * BCB;
    int i0 = ic * IPC;

    unsigned int fb0 = smem_u32(&mbar[0]);
    unsigned int fb1 = smem_u32(&mbar[1]);
    unsigned int eb0 = smem_u32(&mbar[2]);
    unsigned int eb1 = smem_u32(&mbar[3]);
    unsigned int rb0 = smem_u32(&bufs[0]);
    unsigned int rb1 = smem_u32(&bufs[STAGE_N]);

    if (tid == 0) {
        mbar_init(fb0, 1);  mbar_init(fb1, 1);
        mbar_init(eb0, 16); mbar_init(eb1, 16);
    }

    for (int idx = tid; idx < IPC * BCB; idx += MAIN_TPB) {
        int il = idx >> 10, bl = idx & (BCB - 1);
        z_s[idx] = g_Zt[(i0 + il) * BATCHN + b0 + bl];
    }
    __syncthreads();   // mbar init + z_s visible

    const int NS = IPC * DDEPTH;   // 112
    auto src_of = [&](int s) -> const float* {
        int il = s / DDEPTH;
        int d  = s - il * DDEPTH;
        return g_T + (size_t)(d * IND + i0 + il) * (NT * TROW) + (size_t)hc * (NT * CHUNKF);
    };

    if (tid == 0) {
        mbar_expect(fb0, STAGE_BYTES); bulk_g2s(rb0, src_of(0), STAGE_BYTES, fb0);
        mbar_expect(fb1, STAGE_BYTES); bulk_g2s(rb1, src_of(1), STAGE_BYTES, fb1);
    }

    float2 acc[32];
    #pragma unroll
    for (int j = 0; j < 32; j++) acc[j] = make_float2(0.f, 0.f);

    int il = 0, d = 0;
    for (int s = 0; s < NS; s++) {
        // prefetch step inputs BEFORE the full-wait (independent of buffer)
        const uint4* tm = (const uint4*)
            (g_tmap + (size_t)(d * IND + i0 + il) * BATCHN + b0 + bg * 32);
        uint4 ta = tm[0], tb = tm[1];
        const float* zb = z_s + il * BCB + bg * 32;

        unsigned int par = (s >> 1) & 1;
        mbar_wait((s & 1) ? fb1 : fb0, par);

        const float4* rb = bufs + (size_t)(s & 1) * STAGE_N;

        #define STEP4(W, Z4, JA) { \
            unsigned int w_ = (W); \
            float4 z4 = (Z4); \
            float4 v0 = rb[(w_ & 255u) * 16 + hp]; \
            float4 v1 = rb[((w_ >> 8) & 255u) * 16 + hp]; \
            float4 v2 = rb[((w_ >> 16) & 255u) * 16 + hp]; \
            float4 v3 = rb[(w_ >> 24) * 16 + hp]; \
            acc[JA+0].x = fmaf(z4.x, v0.x, acc[JA+0].x - v0.y); \
            acc[JA+0].y = fmaf(z4.x, v0.z, acc[JA+0].y - v0.w); \
            acc[JA+1].x = fmaf(z4.y, v1.x, acc[JA+1].x - v1.y); \
            acc[JA+1].y = fmaf(z4.y, v1.z, acc[JA+1].y - v1.w); \
            acc[JA+2].x = fmaf(z4.z, v2.x, acc[JA+2].x - v2.y); \
            acc[JA+2].y = fmaf(z4.z, v2.z, acc[JA+2].y - v2.w); \
            acc[JA+3].x = fmaf(z4.w, v3.x, acc[JA+3].x - v3.y); \
            acc[JA+3].y = fmaf(z4.w, v3.z, acc[JA+3].y - v3.w); \
        }
        STEP4(ta.x, ((const float4*)zb)[0], 0)
        STEP4(ta.y, ((const float4*)zb)[1], 4)
        STEP4(ta.z, ((const float4*)zb)[2], 8)
        STEP4(ta.w, ((const float4*)zb)[3], 12)
        STEP4(tb.x, ((const float4*)zb)[4], 16)
        STEP4(tb.y, ((const float4*)zb)[5], 20)
        STEP4(tb.z, ((const float4*)zb)[6], 24)
        STEP4(tb.w, ((const float4*)zb)[7], 28)
        #undef STEP4

        __syncwarp();                                          // all lanes' reads done
        if ((tid & 31) == 0) mbar_arrive((s & 1) ? eb1 : eb0); // warp consumed buffer s

        if (tid == 0 && s + 2 < NS) {
            mbar_wait((s & 1) ? eb1 : eb0, par);   // all 16 warps consumed buffer s
            unsigned int fbn = (s & 1) ? fb1 : fb0;
            mbar_expect(fbn, STAGE_BYTES);
            bulk_g2s((s & 1) ? rb1 : rb0, src_of(s + 2), STAGE_BYTES, fbn);
        }
        if (++d == DDEPTH) { d = 0; il++; }
    }

    int h0 = (hc * 16 + hp) * 2;
    float* outp = g_Hp + (size_t)ic * BATCHN * HIDN;
    #pragma unroll
    for (int j = 0; j < 32; j++) {
        int b = b0 + bg * 32 + j;
        *(float2*)&outp[(size_t)b * HIDN + h0] = acc[j];
    }
}

// ---------------- 7. MLP head ----------------
__global__ void k_zstat() {
    int t = threadIdx.x;
    g_sum[t] = 0.0; g_sumsq[t] = 0.0;
}

__device__ __forceinline__ float gelu_exact(float y) {
    return 0.5f * y * (1.0f + erff(y * 0.70710678118654752440f));
}

// 512 threads: hxc = tid&255 (h column), bh = tid>>8 (batch half, 8 b each).
// 16 warps/SM for latency hiding (was 8 → issue-starved at 50us/launch).
// act==0: src = g_Hp, sum NIC partials. act==1: BN(prev params)+GELU on src.
__global__ void __launch_bounds__(512) k_gemm(const float* __restrict__ W,
                                              const float* __restrict__ bias,
                                              const float* __restrict__ src,
                                              float* __restrict__ dst,
                                              int act) {
    __shared__ float Hs[16 * HIDN];
    int b0 = blockIdx.x * 16;
    int tid = threadIdx.x;
    for (int idx = tid; idx < 16 * HIDN; idx += 512) {
        size_t off = (size_t)b0 * HIDN + idx;
        float v;
        if (act) {
            v = src[off];
            float2 p = g_bnp[idx & (HIDN - 1)];
            v = gelu_exact(fmaf(v, p.x, p.y));
        } else {
            v = 0.f;
            #pragma unroll
            for (int p = 0; p < NIC; p++)
                v += src[(size_t)p * BATCHN * HIDN + off];
        }
        Hs[idx] = v;
    }
    __syncthreads();

    int hxc = tid & 255;
    int bh  = tid >> 8;              // 0 or 1 -> batches bh*8 .. bh*8+7
    const float* HsB = Hs + bh * 8 * HIDN;

    float acc[8];
    #pragma unroll
    for (int b = 0; b < 8; b++) acc[b] = 0.f;
    for (int k4 = 0; k4 < HIDN / 4; k4++) {
        float w0 = W[(4 * k4 + 0) * HIDN + hxc];
        float w1 = W[(4 * k4 + 1) * HIDN + hxc];
        float w2 = W[(4 * k4 + 2) * HIDN + hxc];
        float w3 = W[(4 * k4 + 3) * HIDN + hxc];
        #pragma unroll
        for (int b = 0; b < 8; b++) {
            float4 hv = *(const float4*)&HsB[b * HIDN + 4 * k4];
            acc[b] = fmaf(hv.x, w0, fmaf(hv.y, w1, fmaf(hv.z, w2, fmaf(hv.w, w3, acc[b]))));
        }
    }
    float bsv = bias[hxc];
    double s1 = 0.0, s2 = 0.0;
    #pragma unroll
    for (int b = 0; b < 8; b++) {
        float y = acc[b] + bsv;
        dst[(size_t)(b0 + bh * 8 + b) * HIDN + hxc] = y;
        s1 += (double)y;
        s2 += (double)y * (double)y;
    }
    atomicAdd(&g_sum[hxc], s1);
    atomicAdd(&g_sumsq[hxc], s2);
}

__global__ void k_bnfin(const float* __restrict__ gamma, const float* __restrict__ beta) {
    int h = threadIdx.x;
    double mean = g_sum[h] / (double)BATCHN;
    double var  = g_sumsq[h] / (double)BATCHN - mean * mean;
    float scale = gamma[h] * rsqrtf((float)var + 1e-5f);
    float shift = beta[h] - (float)mean * scale;
    g_bnp[h] = make_float2(scale, shift);
    g_sum[h] = 0.0; g_sumsq[h] = 0.0;
}

__global__ void k_final(const float* __restrict__ Wout, const float* __restrict__ bout,
                        float* __restrict__ out) {
    int b = blockIdx.x * 8 + (threadIdx.x >> 5);
    int lane = threadIdx.x & 31;
    const float* hr = g_Hb + (size_t)b * HIDN;
    float s = 0.f;
    #pragma unroll
    for (int k = lane; k < HIDN; k += 32) {
        float2 p = g_bnp[k];
        float y = gelu_exact(fmaf(hr[k], p.x, p.y));
        s = fmaf(y, Wout[k], s);
    }
    #pragma unroll
    for (int o = 16; o > 0; o >>= 1) s += __shfl_down_sync(0xffffffffu, s, o);
    if (lane == 0) out[b] = s + bout[0];
}

// ---------------- launch ----------------
extern "C" void kernel_launch(void* const* d_in, const int* in_sizes, int n_in,
                              void* d_out, int out_size) {
    const float* x     = (const float*)d_in[0];
    const float* grids = (const float*)d_in[1];
    const float* fs    = (const float*)d_in[2];
    const float* ds    = (const float*)d_in[3];
    const float* mlpW  = (const float*)d_in[4];
    const float* mlpb  = (const float*)d_in[5];
    const float* gamma = (const float*)d_in[6];
    const float* beta  = (const float*)d_in[7];
    const float* Wout  = (const float*)d_in[8];
    const float* bout  = (const float*)d_in[9];
    float* out = (float*)d_out;

    float* Ha; float* Hb; float* Hp;
    cudaGetSymbolAddress((void**)&Ha, g_Ha);
    cudaGetSymbolAddress((void**)&Hb, g_Hb);
    cudaGetSymbolAddress((void**)&Hp, g_Hp);

    cudaFuncSetAttribute(k_main, cudaFuncAttributeMaxDynamicSharedMemorySize, SMEM_MAIN);

    k_minmax<<<IND, 256>>>(x);
    k_z<<<(BATCHN * IND + 255) / 256, 256>>>(x);
    k_sort<<<DDEPTH * IND, GRIDN>>>(grids);
    k_table<<<DDEPTH * IND, 128>>>(fs, ds);
    k_tmap<<<DDEPTH * IND, 256>>>();
    k_main<<<128, MAIN_TPB, SMEM_MAIN>>>();

    k_zstat<<<1, HIDN>>>();
    k_gemm<<<BATCHN / 16, 512>>>(mlpW + 0 * HIDN * HIDN, mlpb + 0 * HIDN, Hp, Hb, 0);
    k_bnfin<<<1, HIDN>>>(gamma + 0 * HIDN, beta + 0 * HIDN);
    k_gemm<<<BATCHN / 16, 512>>>(mlpW + 1 * HIDN * HIDN, mlpb + 1 * HIDN, Hb, Ha, 1);
    k_bnfin<<<1, HIDN>>>(gamma + 1 * HIDN, beta + 1 * HIDN);
    k_gemm<<<BATCHN / 16, 512>>>(mlpW + 2 * HIDN * HIDN, mlpb + 2 * HIDN, Ha, Hb, 1);
    k_bnfin<<<1, HIDN>>>(gamma + 2 * HIDN, beta + 2 * HIDN);
    k_final<<<BATCHN / 8, 256>>>(Wout, bout, out);
}

// round 16
// speedup vs baseline: 1.4780x; 1.4780x over previous
#include <cuda_runtime.h>
#include <math.h>
#include <float.h>

#define DDEPTH 7
#define IND   128
#define GRIDN 128
#define HIDN  256
#define BATCHN 2048
#define NT    129          // t in 0..128
#define TROW  512          // floats per (d,i) across all h

// k_main tiling: 2 batch-chunks (halved staging multiplicity)
#define MAIN_TPB 512
#define BCB   1024         // batches per CTA
#define IPC   16           // i's per CTA
#define NIC   8            // i-chunk count (128/IPC)
#define CHUNKF 64          // floats per t-row within one 32-h chunk
#define STAGE_N (NT * 16)               // 2064 float4 per buffer
#define STAGE_BYTES (NT * CHUNKF * 4)   // 33024
#define SMEM_MAIN (2 * STAGE_N * 16 + IPC * BCB * 4 + 64)   // 131648

// ---------------- scratch (static device memory; no allocation) ----------------
__device__ float g_xmin[IND];
__device__ float g_xmax[IND];
__device__ float g_Zt[IND * BATCHN];             // z transposed: [i][b]
__device__ float g_sg[DDEPTH * IND * GRIDN];     // sorted grids
__device__ int   g_perm[DDEPTH * IND * GRIDN];   // permutation
// layout: [d][i][hc8][t][64 floats]  (c_d folded in)
__device__ float g_T[(size_t)DDEPTH * IND * NT * TROW];
__device__ unsigned char g_tmap[(size_t)DDEPTH * IND * BATCHN];
__device__ float g_Hp[(size_t)NIC * BATCHN * HIDN];       // i-split partials
__device__ float g_Ha[BATCHN * HIDN];
__device__ float g_Hb[BATCHN * HIDN];
__device__ double g_sum[HIDN];
__device__ double g_sumsq[HIDN];
__device__ float2 g_bnp[HIDN];

// ---------------- mbarrier + bulk-copy helpers ----------------
__device__ __forceinline__ unsigned int smem_u32(const void* p) {
    return (unsigned int)__cvta_generic_to_shared(p);
}
__device__ __forceinline__ void mbar_init(unsigned int a, unsigned int cnt) {
    asm volatile("mbarrier.init.shared.b64 [%0], %1;" :: "r"(a), "r"(cnt) : "memory");
}
__device__ __forceinline__ void mbar_expect(unsigned int a, unsigned int tx) {
    asm volatile("mbarrier.arrive.expect_tx.shared.b64 _, [%0], %1;" :: "r"(a), "r"(tx) : "memory");
}
__device__ __forceinline__ void mbar_arrive(unsigned int a) {
    asm volatile("mbarrier.arrive.release.cta.shared.b64 _, [%0];" :: "r"(a) : "memory");
}
__device__ __forceinline__ void bulk_g2s(unsigned int dst, const void* src,
                                         unsigned int bytes, unsigned int mbar) {
    asm volatile("cp.async.bulk.shared::cta.global.mbarrier::complete_tx::bytes [%0], [%1], %2, [%3];"
                 :: "r"(dst), "l"(src), "r"(bytes), "r"(mbar) : "memory");
}
__device__ __forceinline__ void mbar_wait(unsigned int a, unsigned int parity) {
    asm volatile(
        "{\n\t"
        ".reg .pred P;\n\t"
        "W_%=:\n\t"
        "mbarrier.try_wait.parity.acquire.cta.shared::cta.b64 P, [%0], %1;\n\t"
        "@P bra D_%=;\n\t"
        "bra W_%=;\n\t"
        "D_%=:\n\t"
        "}"
        :: "r"(a), "r"(parity) : "memory");
}

// ---------------- 1. per-feature min/max over batch ----------------
__global__ void k_minmax(const float* __restrict__ x) {
    int i = blockIdx.x;
    float mn = FLT_MAX, mx = -FLT_MAX;
    for (int b = threadIdx.x; b < BATCHN; b += blockDim.x) {
        float v = x[b * IND + i];
        mn = fminf(mn, v);
        mx = fmaxf(mx, v);
    }
    __shared__ float smn[256], smx[256];
    smn[threadIdx.x] = mn; smx[threadIdx.x] = mx;
    __syncthreads();
    for (int s = 128; s > 0; s >>= 1) {
        if (threadIdx.x < s) {
            smn[threadIdx.x] = fminf(smn[threadIdx.x], smn[threadIdx.x + s]);
            smx[threadIdx.x] = fmaxf(smx[threadIdx.x], smx[threadIdx.x + s]);
        }
        __syncthreads();
    }
    if (threadIdx.x == 0) { g_xmin[i] = smn[0]; g_xmax[i] = smx[0]; }
}

// ---------------- 2. z transposed: g_Zt[i][b] ----------------
__global__ void k_z(const float* __restrict__ x) {
    int idx = blockIdx.x * blockDim.x + threadIdx.x;
    if (idx < BATCHN * IND) {
        int i = idx & (IND - 1);
        int b = idx >> 7;
        g_Zt[i * BATCHN + b] = (x[idx] - g_xmin[i]) / (g_xmax[i] - g_xmin[i] + 1e-6f);
    }
}

// ---------------- 3. sort grids per (d,i) via rank ----------------
__global__ void k_sort(const float* __restrict__ grids) {
    int di = blockIdx.x;
    int t  = threadIdx.x;
    __shared__ float sg[GRIDN];
    float g = grids[di * GRIDN + t];
    sg[t] = g;
    __syncthreads();
    int r = 0;
    #pragma unroll 8
    for (int j = 0; j < GRIDN; j++) {
        float gj = sg[j];
        r += (gj < g) || (gj == g && j < t);
    }
    g_sg[di * GRIDN + r]   = g;
    g_perm[di * GRIDN + r] = t;
}

// ---------------- 4. prefix tables with c_d folded; 32-h chunked layout ----------------
// 128 threads, each owns h pair (2*h2, 2*h2+1): float2 loads, float4 stores.
__global__ void __launch_bounds__(128) k_table(const float* __restrict__ fs,
                                               const float* __restrict__ ds) {
    __shared__ float ssg[GRIDN];
    __shared__ int   spm[GRIDN];
    int di = blockIdx.x;
    int d  = di >> 7;
    int h2 = threadIdx.x;               // 0..127
    ssg[h2] = g_sg[di * GRIDN + h2];
    spm[h2] = g_perm[di * GRIDN + h2];

    float w[DDEPTH], m = -FLT_MAX;
    for (int k = 0; k < DDEPTH; k++) m = fmaxf(m, ds[k]);
    float ssum = 0.f;
    for (int k = 0; k < DDEPTH; k++) { w[k] = expf(ds[k] - m); ssum += w[k]; }
    float cd = 0.f;
    for (int k = DDEPTH - 1; k >= d; --k) cd += w[k] / ssum;
    __syncthreads();

    const float* fbase = fs + (size_t)di * GRIDN * HIDN + 2 * h2;
    // chunk hc = h2>>4 (16 h-pairs per chunk); float offset in 64-float row = (h2&15)*4
    float* base = g_T + (size_t)di * NT * TROW + (h2 >> 4) * (NT * CHUNKF) + (h2 & 15) * 4;
    float a10 = 0.f, a20 = 0.f, a11 = 0.f, a21 = 0.f;
    *(float4*)base = make_float4(0.f, 0.f, 0.f, 0.f);
    for (int t0 = 0; t0 < GRIDN; t0 += 4) {
        int p0 = spm[t0 + 0], p1 = spm[t0 + 1], p2 = spm[t0 + 2], p3 = spm[t0 + 3];
        float2 f0 = *(const float2*)(fbase + p0 * HIDN);
        float2 f1 = *(const float2*)(fbase + p1 * HIDN);
        float2 f2 = *(const float2*)(fbase + p2 * HIDN);
        float2 f3 = *(const float2*)(fbase + p3 * HIDN);
        float g0 = ssg[t0 + 0], g1 = ssg[t0 + 1], g2 = ssg[t0 + 2], g3 = ssg[t0 + 3];
        a10 += f0.x; a20 = fmaf(g0, f0.x, a20);
        a11 += f0.y; a21 = fmaf(g0, f0.y, a21);
        *(float4*)(base + (size_t)(t0 + 1) * CHUNKF) = make_float4(cd*a10, cd*a20, cd*a11, cd*a21);
        a10 += f1.x; a20 = fmaf(g1, f1.x, a20);
        a11 += f1.y; a21 = fmaf(g1, f1.y, a21);
        *(float4*)(base + (size_t)(t0 + 2) * CHUNKF) = make_float4(cd*a10, cd*a20, cd*a11, cd*a21);
        a10 += f2.x; a20 = fmaf(g2, f2.x, a20);
        a11 += f2.y; a21 = fmaf(g2, f2.y, a21);
        *(float4*)(base + (size_t)(t0 + 3) * CHUNKF) = make_float4(cd*a10, cd*a20, cd*a11, cd*a21);
        a10 += f3.x; a20 = fmaf(g3, f3.x, a20);
        a11 += f3.y; a21 = fmaf(g3, f3.y, a21);
        *(float4*)(base + (size_t)(t0 + 4) * CHUNKF) = make_float4(cd*a10, cd*a20, cd*a11, cd*a21);
    }
}

// ---------------- 5. t[d,i,b] = #{ g < z } ----------------
__global__ void k_tmap() {
    int di = blockIdx.x;
    __shared__ float sg[GRIDN];
    if (threadIdx.x < GRIDN) sg[threadIdx.x] = g_sg[di * GRIDN + threadIdx.x];
    __syncthreads();
    int i = di & (IND - 1);
    for (int b = threadIdx.x; b < BATCHN; b += blockDim.x) {
        float z = g_Zt[i * BATCHN + b];
        int t = 0;
        #pragma unroll
        for (int s = 64; s > 0; s >>= 1) {
            int nt = t + s;
            if (nt <= GRIDN && sg[nt - 1] < z) t = nt;
        }
        g_tmap[(size_t)di * BATCHN + b] = (unsigned char)t;
    }
}

// ---------------- 6. main kernel: 1024-b CTAs, barrier-free mbarrier ring ----------------
// grid = 128: bc = x&1 (1024 b), hc = (x>>1)&7 (32 h), ic = x>>4 (8 chunks of 16 i).
// 512 threads (16 warps): hp = tid&15 (h-pair in chunk), bg = tid>>4 (32 batches each).
// Ring: full[k] (count 1 + expect_tx), empty[k] (count 16, per-warp lane0 arrive).
__global__ void __launch_bounds__(MAIN_TPB, 1) k_main() {
    extern __shared__ float4 dynsmem[];
    float4* bufs = dynsmem;                               // [2][STAGE_N]
    float*  z_s  = (float*)(dynsmem + 2 * STAGE_N);       // [IPC][BCB] 64KB
    unsigned long long* mbar = (unsigned long long*)(z_s + IPC * BCB);  // fb0,fb1,eb0,eb1

    int bc = blockIdx.x & 1;
    int hc = (blockIdx.x >> 1) & 7;
    int ic = blockIdx.x >> 4;
    int tid = threadIdx.x;
    int hp = tid & 15;
    int bg = tid >> 4;          // 0..31
    int b0 = bc * BCB;
    int i0 = ic * IPC;

    unsigned int fb0 = smem_u32(&mbar[0]);
    unsigned int fb1 = smem_u32(&mbar[1]);
    unsigned int eb0 = smem_u32(&mbar[2]);
    unsigned int eb1 = smem_u32(&mbar[3]);
    unsigned int rb0 = smem_u32(&bufs[0]);
    unsigned int rb1 = smem_u32(&bufs[STAGE_N]);

    if (tid == 0) {
        mbar_init(fb0, 1);  mbar_init(fb1, 1);
        mbar_init(eb0, 16); mbar_init(eb1, 16);
    }

    for (int idx = tid; idx < IPC * BCB; idx += MAIN_TPB) {
        int il = idx >> 10, bl = idx & (BCB - 1);
        z_s[idx] = g_Zt[(i0 + il) * BATCHN + b0 + bl];
    }
    __syncthreads();   // mbar init + z_s visible

    const int NS = IPC * DDEPTH;   // 112
    auto src_of = [&](int s) -> const float* {
        int il = s / DDEPTH;
        int d  = s - il * DDEPTH;
        return g_T + (size_t)(d * IND + i0 + il) * (NT * TROW) + (size_t)hc * (NT * CHUNKF);
    };

    if (tid == 0) {
        mbar_expect(fb0, STAGE_BYTES); bulk_g2s(rb0, src_of(0), STAGE_BYTES, fb0);
        mbar_expect(fb1, STAGE_BYTES); bulk_g2s(rb1, src_of(1), STAGE_BYTES, fb1);
    }

    float2 acc[32];
    #pragma unroll
    for (int j = 0; j < 32; j++) acc[j] = make_float2(0.f, 0.f);

    int il = 0, d = 0;
    for (int s = 0; s < NS; s++) {
        // prefetch step inputs BEFORE the full-wait (independent of buffer)
        const uint4* tm = (const uint4*)
            (g_tmap + (size_t)(d * IND + i0 + il) * BATCHN + b0 + bg * 32);
        uint4 ta = tm[0], tb = tm[1];
        const float* zb = z_s + il * BCB + bg * 32;

        unsigned int par = (s >> 1) & 1;
        mbar_wait((s & 1) ? fb1 : fb0, par);

        const float4* rb = bufs + (size_t)(s & 1) * STAGE_N;

        #define STEP4(W, Z4, JA) { \
            unsigned int w_ = (W); \
            float4 z4 = (Z4); \
            float4 v0 = rb[(w_ & 255u) * 16 + hp]; \
            float4 v1 = rb[((w_ >> 8) & 255u) * 16 + hp]; \
            float4 v2 = rb[((w_ >> 16) & 255u) * 16 + hp]; \
            float4 v3 = rb[(w_ >> 24) * 16 + hp]; \
            acc[JA+0].x = fmaf(z4.x, v0.x, acc[JA+0].x - v0.y); \
            acc[JA+0].y = fmaf(z4.x, v0.z, acc[JA+0].y - v0.w); \
            acc[JA+1].x = fmaf(z4.y, v1.x, acc[JA+1].x - v1.y); \
            acc[JA+1].y = fmaf(z4.y, v1.z, acc[JA+1].y - v1.w); \
            acc[JA+2].x = fmaf(z4.z, v2.x, acc[JA+2].x - v2.y); \
            acc[JA+2].y = fmaf(z4.z, v2.z, acc[JA+2].y - v2.w); \
            acc[JA+3].x = fmaf(z4.w, v3.x, acc[JA+3].x - v3.y); \
            acc[JA+3].y = fmaf(z4.w, v3.z, acc[JA+3].y - v3.w); \
        }
        STEP4(ta.x, ((const float4*)zb)[0], 0)
        STEP4(ta.y, ((const float4*)zb)[1], 4)
        STEP4(ta.z, ((const float4*)zb)[2], 8)
        STEP4(ta.w, ((const float4*)zb)[3], 12)
        STEP4(tb.x, ((const float4*)zb)[4], 16)
        STEP4(tb.y, ((const float4*)zb)[5], 20)
        STEP4(tb.z, ((const float4*)zb)[6], 24)
        STEP4(tb.w, ((const float4*)zb)[7], 28)
        #undef STEP4

        __syncwarp();                                          // all lanes' reads done
        if ((tid & 31) == 0) mbar_arrive((s & 1) ? eb1 : eb0); // warp consumed buffer s

        if (tid == 0 && s + 2 < NS) {
            mbar_wait((s & 1) ? eb1 : eb0, par);   // all 16 warps consumed buffer s
            unsigned int fbn = (s & 1) ? fb1 : fb0;
            mbar_expect(fbn, STAGE_BYTES);
            bulk_g2s((s & 1) ? rb1 : rb0, src_of(s + 2), STAGE_BYTES, fbn);
        }
        if (++d == DDEPTH) { d = 0; il++; }
    }

    int h0 = (hc * 16 + hp) * 2;
    float* outp = g_Hp + (size_t)ic * BATCHN * HIDN;
    #pragma unroll
    for (int j = 0; j < 32; j++) {
        int b = b0 + bg * 32 + j;
        *(float2*)&outp[(size_t)b * HIDN + h0] = acc[j];
    }
}

// ---------------- 7. MLP head ----------------
__global__ void k_zstat() {
    int t = threadIdx.x;
    g_sum[t] = 0.0; g_sumsq[t] = 0.0;
}

__device__ __forceinline__ float gelu_exact(float y) {
    return 0.5f * y * (1.0f + erff(y * 0.70710678118654752440f));
}

// b-tile 8, grid 256 (every SM covered, most get 2 CTAs = 16 warps), 256 threads.
// Thread = h column, 8 accs. One W pass per CTA in one order (no duplicated stream).
// act==0: src = g_Hp, sum NIC partials. act==1: BN(prev params)+GELU on src.
__global__ void __launch_bounds__(256) k_gemm(const float* __restrict__ W,
                                              const float* __restrict__ bias,
                                              const float* __restrict__ src,
                                              float* __restrict__ dst,
                                              int act) {
    __shared__ float Hs[8 * HIDN];    // 8 KB
    int b0 = blockIdx.x * 8;
    int tid = threadIdx.x;
    for (int idx = tid; idx < 8 * HIDN; idx += 256) {
        size_t off = (size_t)b0 * HIDN + idx;
        float v;
        if (act) {
            v = src[off];
            float2 p = g_bnp[idx & (HIDN - 1)];
            v = gelu_exact(fmaf(v, p.x, p.y));
        } else {
            v = 0.f;
            #pragma unroll
            for (int p = 0; p < NIC; p++)
                v += src[(size_t)p * BATCHN * HIDN + off];
        }
        Hs[idx] = v;
    }
    __syncthreads();

    float acc[8];
    #pragma unroll
    for (int b = 0; b < 8; b++) acc[b] = 0.f;
    int hxc = tid;
    #pragma unroll 2
    for (int k4 = 0; k4 < HIDN / 4; k4++) {
        float w0 = W[(4 * k4 + 0) * HIDN + hxc];
        float w1 = W[(4 * k4 + 1) * HIDN + hxc];
        float w2 = W[(4 * k4 + 2) * HIDN + hxc];
        float w3 = W[(4 * k4 + 3) * HIDN + hxc];
        #pragma unroll
        for (int b = 0; b < 8; b++) {
            float4 hv = *(const float4*)&Hs[b * HIDN + 4 * k4];
            acc[b] = fmaf(hv.x, w0, fmaf(hv.y, w1, fmaf(hv.z, w2, fmaf(hv.w, w3, acc[b]))));
        }
    }
    float bsv = bias[hxc];
    double s1 = 0.0, s2 = 0.0;
    #pragma unroll
    for (int b = 0; b < 8; b++) {
        float y = acc[b] + bsv;
        dst[(size_t)(b0 + b) * HIDN + hxc] = y;
        s1 += (double)y;
        s2 += (double)y * (double)y;
    }
    atomicAdd(&g_sum[hxc], s1);
    atomicAdd(&g_sumsq[hxc], s2);
}

__global__ void k_bnfin(const float* __restrict__ gamma, const float* __restrict__ beta) {
    int h = threadIdx.x;
    double mean = g_sum[h] / (double)BATCHN;
    double var  = g_sumsq[h] / (double)BATCHN - mean * mean;
    float scale = gamma[h] * rsqrtf((float)var + 1e-5f);
    float shift = beta[h] - (float)mean * scale;
    g_bnp[h] = make_float2(scale, shift);
    g_sum[h] = 0.0; g_sumsq[h] = 0.0;
}

__global__ void k_final(const float* __restrict__ Wout, const float* __restrict__ bout,
                        float* __restrict__ out) {
    int b = blockIdx.x * 8 + (threadIdx.x >> 5);
    int lane = threadIdx.x & 31;
    const float* hr = g_Hb + (size_t)b * HIDN;
    float s = 0.f;
    #pragma unroll
    for (int k = lane; k < HIDN; k += 32) {
        float2 p = g_bnp[k];
        float y = gelu_exact(fmaf(hr[k], p.x, p.y));
        s = fmaf(y, Wout[k], s);
    }
    #pragma unroll
    for (int o = 16; o > 0; o >>= 1) s += __shfl_down_sync(0xffffffffu, s, o);
    if (lane == 0) out[b] = s + bout[0];
}

// ---------------- launch ----------------
extern "C" void kernel_launch(void* const* d_in, const int* in_sizes, int n_in,
                              void* d_out, int out_size) {
    const float* x     = (const float*)d_in[0];
    const float* grids = (const float*)d_in[1];
    const float* fs    = (const float*)d_in[2];
    const float* ds    = (const float*)d_in[3];
    const float* mlpW  = (const float*)d_in[4];
    const float* mlpb  = (const float*)d_in[5];
    const float* gamma = (const float*)d_in[6];
    const float* beta  = (const float*)d_in[7];
    const float* Wout  = (const float*)d_in[8];
    const float* bout  = (const float*)d_in[9];
    float* out = (float*)d_out;

    float* Ha; float* Hb; float* Hp;
    cudaGetSymbolAddress((void**)&Ha, g_Ha);
    cudaGetSymbolAddress((void**)&Hb, g_Hb);
    cudaGetSymbolAddress((void**)&Hp, g_Hp);

    cudaFuncSetAttribute(k_main, cudaFuncAttributeMaxDynamicSharedMemorySize, SMEM_MAIN);

    k_minmax<<<IND, 256>>>(x);
    k_z<<<(BATCHN * IND + 255) / 256, 256>>>(x);
    k_sort<<<DDEPTH * IND, GRIDN>>>(grids);
    k_table<<<DDEPTH * IND, 128>>>(fs, ds);
    k_tmap<<<DDEPTH * IND, 256>>>();
    k_main<<<128, MAIN_TPB, SMEM_MAIN>>>();

    k_zstat<<<1, HIDN>>>();
    k_gemm<<<BATCHN / 8, 256>>>(mlpW + 0 * HIDN * HIDN, mlpb + 0 * HIDN, Hp, Hb, 0);
    k_bnfin<<<1, HIDN>>>(gamma + 0 * HIDN, beta + 0 * HIDN);
    k_gemm<<<BATCHN / 8, 256>>>(mlpW + 1 * HIDN * HIDN, mlpb + 1 * HIDN, Hb, Ha, 1);
    k_bnfin<<<1, HIDN>>>(gamma + 1 * HIDN, beta + 1 * HIDN);
    k_gemm<<<BATCHN / 8, 256>>>(mlpW + 2 * HIDN * HIDN, mlpb + 2 * HIDN, Ha, Hb, 1);
    k_bnfin<<<1, HIDN>>>(gamma + 2 * HIDN, beta + 2 * HIDN);
    k_final<<<BATCHN / 8, 256>>>(Wout, bout, out);
}

// round 17
// speedup vs baseline: 1.7525x; 1.1858x over previous
#include <cuda_runtime.h>
#include <math.h>
#include <float.h>

#define DDEPTH 7
#define IND   128
#define GRIDN 128
#define HIDN  256
#define BATCHN 2048
#define NT    129          // t in 0..128
#define TROW  512          // floats per (d,i) across all h

// k_main tiling: 2 batch-chunks (halved staging multiplicity)
#define MAIN_TPB 512
#define BCB   1024         // batches per CTA
#define IPC   16           // i's per CTA
#define NIC   8            // i-chunk count (128/IPC)
#define CHUNKF 64          // floats per t-row within one 32-h chunk
#define STAGE_N (NT * 16)               // 2064 float4 per buffer
#define STAGE_BYTES (NT * CHUNKF * 4)   // 33024
#define SMEM_MAIN (2 * STAGE_N * 16 + IPC * BCB * 4 + 64)   // 131648

// k_gemm W-streaming
#define WCHUNK_K 32                     // k-rows per stage
#define WCHUNK_F (WCHUNK_K * HIDN)      // 8192 floats = 32KB
#define NWCHUNK  (HIDN / WCHUNK_K)      // 8 stages
#define SMEM_GEMM ((8 * HIDN + 2 * WCHUNK_F) * 4 + 64)   // 73792

// ---------------- scratch (static device memory; no allocation) ----------------
__device__ float g_xmin[IND];
__device__ float g_xmax[IND];
__device__ float g_Zt[IND * BATCHN];             // z transposed: [i][b]
__device__ float g_sg[DDEPTH * IND * GRIDN];     // sorted grids
__device__ int   g_perm[DDEPTH * IND * GRIDN];   // permutation
// layout: [d][i][hc8][t][64 floats]  (c_d folded in)
__device__ float g_T[(size_t)DDEPTH * IND * NT * TROW];
__device__ unsigned char g_tmap[(size_t)DDEPTH * IND * BATCHN];
__device__ float g_Hp[(size_t)NIC * BATCHN * HIDN];       // i-split partials
__device__ float g_Ha[BATCHN * HIDN];
__device__ float g_Hb[BATCHN * HIDN];
__device__ double g_sum[HIDN];
__device__ double g_sumsq[HIDN];
__device__ float2 g_bnp[HIDN];

// ---------------- mbarrier + bulk-copy helpers ----------------
__device__ __forceinline__ unsigned int smem_u32(const void* p) {
    return (unsigned int)__cvta_generic_to_shared(p);
}
__device__ __forceinline__ void mbar_init(unsigned int a, unsigned int cnt) {
    asm volatile("mbarrier.init.shared.b64 [%0], %1;" :: "r"(a), "r"(cnt) : "memory");
}
__device__ __forceinline__ void mbar_expect(unsigned int a, unsigned int tx) {
    asm volatile("mbarrier.arrive.expect_tx.shared.b64 _, [%0], %1;" :: "r"(a), "r"(tx) : "memory");
}
__device__ __forceinline__ void mbar_arrive(unsigned int a) {
    asm volatile("mbarrier.arrive.release.cta.shared.b64 _, [%0];" :: "r"(a) : "memory");
}
__device__ __forceinline__ void bulk_g2s(unsigned int dst, const void* src,
                                         unsigned int bytes, unsigned int mbar) {
    asm volatile("cp.async.bulk.shared::cta.global.mbarrier::complete_tx::bytes [%0], [%1], %2, [%3];"
                 :: "r"(dst), "l"(src), "r"(bytes), "r"(mbar) : "memory");
}
__device__ __forceinline__ void mbar_wait(unsigned int a, unsigned int parity) {
    asm volatile(
        "{\n\t"
        ".reg .pred P;\n\t"
        "W_%=:\n\t"
        "mbarrier.try_wait.parity.acquire.cta.shared::cta.b64 P, [%0], %1;\n\t"
        "@P bra D_%=;\n\t"
        "bra W_%=;\n\t"
        "D_%=:\n\t"
        "}"
        :: "r"(a), "r"(parity) : "memory");
}

// ---------------- 1. per-feature min/max over batch ----------------
__global__ void k_minmax(const float* __restrict__ x) {
    int i = blockIdx.x;
    float mn = FLT_MAX, mx = -FLT_MAX;
    for (int b = threadIdx.x; b < BATCHN; b += blockDim.x) {
        float v = x[b * IND + i];
        mn = fminf(mn, v);
        mx = fmaxf(mx, v);
    }
    __shared__ float smn[256], smx[256];
    smn[threadIdx.x] = mn; smx[threadIdx.x] = mx;
    __syncthreads();
    for (int s = 128; s > 0; s >>= 1) {
        if (threadIdx.x < s) {
            smn[threadIdx.x] = fminf(smn[threadIdx.x], smn[threadIdx.x + s]);
            smx[threadIdx.x] = fmaxf(smx[threadIdx.x], smx[threadIdx.x + s]);
        }
        __syncthreads();
    }
    if (threadIdx.x == 0) { g_xmin[i] = smn[0]; g_xmax[i] = smx[0]; }
}

// ---------------- 2. z transposed: g_Zt[i][b] ----------------
__global__ void k_z(const float* __restrict__ x) {
    int idx = blockIdx.x * blockDim.x + threadIdx.x;
    if (idx < BATCHN * IND) {
        int i = idx & (IND - 1);
        int b = idx >> 7;
        g_Zt[i * BATCHN + b] = (x[idx] - g_xmin[i]) / (g_xmax[i] - g_xmin[i] + 1e-6f);
    }
}

// ---------------- 3. sort grids per (d,i) via rank ----------------
__global__ void k_sort(const float* __restrict__ grids) {
    int di = blockIdx.x;
    int t  = threadIdx.x;
    __shared__ float sg[GRIDN];
    float g = grids[di * GRIDN + t];
    sg[t] = g;
    __syncthreads();
    int r = 0;
    #pragma unroll 8
    for (int j = 0; j < GRIDN; j++) {
        float gj = sg[j];
        r += (gj < g) || (gj == g && j < t);
    }
    g_sg[di * GRIDN + r]   = g;
    g_perm[di * GRIDN + r] = t;
}

// ---------------- 4. prefix tables with c_d folded; 32-h chunked layout ----------------
// 128 threads, each owns h pair (2*h2, 2*h2+1): float2 loads, float4 stores.
__global__ void __launch_bounds__(128) k_table(const float* __restrict__ fs,
                                               const float* __restrict__ ds) {
    __shared__ float ssg[GRIDN];
    __shared__ int   spm[GRIDN];
    int di = blockIdx.x;
    int d  = di >> 7;
    int h2 = threadIdx.x;               // 0..127
    ssg[h2] = g_sg[di * GRIDN + h2];
    spm[h2] = g_perm[di * GRIDN + h2];

    float w[DDEPTH], m = -FLT_MAX;
    for (int k = 0; k < DDEPTH; k++) m = fmaxf(m, ds[k]);
    float ssum = 0.f;
    for (int k = 0; k < DDEPTH; k++) { w[k] = expf(ds[k] - m); ssum += w[k]; }
    float cd = 0.f;
    for (int k = DDEPTH - 1; k >= d; --k) cd += w[k] / ssum;
    __syncthreads();

    const float* fbase = fs + (size_t)di * GRIDN * HIDN + 2 * h2;
    // chunk hc = h2>>4 (16 h-pairs per chunk); float offset in 64-float row = (h2&15)*4
    float* base = g_T + (size_t)di * NT * TROW + (h2 >> 4) * (NT * CHUNKF) + (h2 & 15) * 4;
    float a10 = 0.f, a20 = 0.f, a11 = 0.f, a21 = 0.f;
    *(float4*)base = make_float4(0.f, 0.f, 0.f, 0.f);
    for (int t0 = 0; t0 < GRIDN; t0 += 4) {
        int p0 = spm[t0 + 0], p1 = spm[t0 + 1], p2 = spm[t0 + 2], p3 = spm[t0 + 3];
        float2 f0 = *(const float2*)(fbase + p0 * HIDN);
        float2 f1 = *(const float2*)(fbase + p1 * HIDN);
        float2 f2 = *(const float2*)(fbase + p2 * HIDN);
        float2 f3 = *(const float2*)(fbase + p3 * HIDN);
        float g0 = ssg[t0 + 0], g1 = ssg[t0 + 1], g2 = ssg[t0 + 2], g3 = ssg[t0 + 3];
        a10 += f0.x; a20 = fmaf(g0, f0.x, a20);
        a11 += f0.y; a21 = fmaf(g0, f0.y, a21);
        *(float4*)(base + (size_t)(t0 + 1) * CHUNKF) = make_float4(cd*a10, cd*a20, cd*a11, cd*a21);
        a10 += f1.x; a20 = fmaf(g1, f1.x, a20);
        a11 += f1.y; a21 = fmaf(g1, f1.y, a21);
        *(float4*)(base + (size_t)(t0 + 2) * CHUNKF) = make_float4(cd*a10, cd*a20, cd*a11, cd*a21);
        a10 += f2.x; a20 = fmaf(g2, f2.x, a20);
        a11 += f2.y; a21 = fmaf(g2, f2.y, a21);
        *(float4*)(base + (size_t)(t0 + 3) * CHUNKF) = make_float4(cd*a10, cd*a20, cd*a11, cd*a21);
        a10 += f3.x; a20 = fmaf(g3, f3.x, a20);
        a11 += f3.y; a21 = fmaf(g3, f3.y, a21);
        *(float4*)(base + (size_t)(t0 + 4) * CHUNKF) = make_float4(cd*a10, cd*a20, cd*a11, cd*a21);
    }
}

// ---------------- 5. t[d,i,b] = #{ g < z } ----------------
__global__ void k_tmap() {
    int di = blockIdx.x;
    __shared__ float sg[GRIDN];
    if (threadIdx.x < GRIDN) sg[threadIdx.x] = g_sg[di * GRIDN + threadIdx.x];
    __syncthreads();
    int i = di & (IND - 1);
    for (int b = threadIdx.x; b < BATCHN; b += blockDim.x) {
        float z = g_Zt[i * BATCHN + b];
        int t = 0;
        #pragma unroll
        for (int s = 64; s > 0; s >>= 1) {
            int nt = t + s;
            if (nt <= GRIDN && sg[nt - 1] < z) t = nt;
        }
        g_tmap[(size_t)di * BATCHN + b] = (unsigned char)t;
    }
}

// ---------------- 6. main kernel: 1024-b CTAs, barrier-free mbarrier ring ----------------
// grid = 128: bc = x&1 (1024 b), hc = (x>>1)&7 (32 h), ic = x>>4 (8 chunks of 16 i).
// 512 threads (16 warps): hp = tid&15 (h-pair in chunk), bg = tid>>4 (32 batches each).
// Ring: full[k] (count 1 + expect_tx), empty[k] (count 16, per-warp lane0 arrive).
__global__ void __launch_bounds__(MAIN_TPB, 1) k_main() {
    extern __shared__ float4 dynsmem[];
    float4* bufs = dynsmem;                               // [2][STAGE_N]
    float*  z_s  = (float*)(dynsmem + 2 * STAGE_N);       // [IPC][BCB] 64KB
    unsigned long long* mbar = (unsigned long long*)(z_s + IPC * BCB);  // fb0,fb1,eb0,eb1

    int bc = blockIdx.x & 1;
    int hc = (blockIdx.x >> 1) & 7;
    int ic = blockIdx.x >> 4;
    int tid = threadIdx.x;
    int hp = tid & 15;
    int bg = tid >> 4;          // 0..31
    int b0 = bc * BCB;
    int i0 = ic * IPC;

    unsigned int fb0 = smem_u32(&mbar[0]);
    unsigned int fb1 = smem_u32(&mbar[1]);
    unsigned int eb0 = smem_u32(&mbar[2]);
    unsigned int eb1 = smem_u32(&mbar[3]);
    unsigned int rb0 = smem_u32(&bufs[0]);
    unsigned int rb1 = smem_u32(&bufs[STAGE_N]);

    if (tid == 0) {
        mbar_init(fb0, 1);  mbar_init(fb1, 1);
        mbar_init(eb0, 16); mbar_init(eb1, 16);
    }

    for (int idx = tid; idx < IPC * BCB; idx += MAIN_TPB) {
        int il = idx >> 10, bl = idx & (BCB - 1);
        z_s[idx] = g_Zt[(i0 + il) * BATCHN + b0 + bl];
    }
    __syncthreads();   // mbar init + z_s visible

    const int NS = IPC * DDEPTH;   // 112
    auto src_of = [&](int s) -> const float* {
        int il = s / DDEPTH;
        int d  = s - il * DDEPTH;
        return g_T + (size_t)(d * IND + i0 + il) * (NT * TROW) + (size_t)hc * (NT * CHUNKF);
    };

    if (tid == 0) {
        mbar_expect(fb0, STAGE_BYTES); bulk_g2s(rb0, src_of(0), STAGE_BYTES, fb0);
        mbar_expect(fb1, STAGE_BYTES); bulk_g2s(rb1, src_of(1), STAGE_BYTES, fb1);
    }

    float2 acc[32];
    #pragma unroll
    for (int j = 0; j < 32; j++) acc[j] = make_float2(0.f, 0.f);

    int il = 0, d = 0;
    for (int s = 0; s < NS; s++) {
        // prefetch step inputs BEFORE the full-wait (independent of buffer)
        const uint4* tm = (const uint4*)
            (g_tmap + (size_t)(d * IND + i0 + il) * BATCHN + b0 + bg * 32);
        uint4 ta = tm[0], tb = tm[1];
        const float* zb = z_s + il * BCB + bg * 32;

        unsigned int par = (s >> 1) & 1;
        mbar_wait((s & 1) ? fb1 : fb0, par);

        const float4* rb = bufs + (size_t)(s & 1) * STAGE_N;

        #define STEP4(W, Z4, JA) { \
            unsigned int w_ = (W); \
            float4 z4 = (Z4); \
            float4 v0 = rb[(w_ & 255u) * 16 + hp]; \
            float4 v1 = rb[((w_ >> 8) & 255u) * 16 + hp]; \
            float4 v2 = rb[((w_ >> 16) & 255u) * 16 + hp]; \
            float4 v3 = rb[(w_ >> 24) * 16 + hp]; \
            acc[JA+0].x = fmaf(z4.x, v0.x, acc[JA+0].x - v0.y); \
            acc[JA+0].y = fmaf(z4.x, v0.z, acc[JA+0].y - v0.w); \
            acc[JA+1].x = fmaf(z4.y, v1.x, acc[JA+1].x - v1.y); \
            acc[JA+1].y = fmaf(z4.y, v1.z, acc[JA+1].y - v1.w); \
            acc[JA+2].x = fmaf(z4.z, v2.x, acc[JA+2].x - v2.y); \
            acc[JA+2].y = fmaf(z4.z, v2.z, acc[JA+2].y - v2.w); \
            acc[JA+3].x = fmaf(z4.w, v3.x, acc[JA+3].x - v3.y); \
            acc[JA+3].y = fmaf(z4.w, v3.z, acc[JA+3].y - v3.w); \
        }
        STEP4(ta.x, ((const float4*)zb)[0], 0)
        STEP4(ta.y, ((const float4*)zb)[1], 4)
        STEP4(ta.z, ((const float4*)zb)[2], 8)
        STEP4(ta.w, ((const float4*)zb)[3], 12)
        STEP4(tb.x, ((const float4*)zb)[4], 16)
        STEP4(tb.y, ((const float4*)zb)[5], 20)
        STEP4(tb.z, ((const float4*)zb)[6], 24)
        STEP4(tb.w, ((const float4*)zb)[7], 28)
        #undef STEP4

        __syncwarp();                                          // all lanes' reads done
        if ((tid & 31) == 0) mbar_arrive((s & 1) ? eb1 : eb0); // warp consumed buffer s

        if (tid == 0 && s + 2 < NS) {
            mbar_wait((s & 1) ? eb1 : eb0, par);   // all 16 warps consumed buffer s
            unsigned int fbn = (s & 1) ? fb1 : fb0;
            mbar_expect(fbn, STAGE_BYTES);
            bulk_g2s((s & 1) ? rb1 : rb0, src_of(s + 2), STAGE_BYTES, fbn);
        }
        if (++d == DDEPTH) { d = 0; il++; }
    }

    int h0 = (hc * 16 + hp) * 2;
    float* outp = g_Hp + (size_t)ic * BATCHN * HIDN;
    #pragma unroll
    for (int j = 0; j < 32; j++) {
        int b = b0 + bg * 32 + j;
        *(float2*)&outp[(size_t)b * HIDN + h0] = acc[j];
    }
}

// ---------------- 7. MLP head ----------------
__global__ void k_zstat() {
    int t = threadIdx.x;
    g_sum[t] = 0.0; g_sumsq[t] = 0.0;
}

__device__ __forceinline__ float gelu_exact(float y) {
    return 0.5f * y * (1.0f + erff(y * 0.70710678118654752440f));
}

// W streamed through smem in 8x 32KB chunks via TMA ring (kills the per-thread
// 64-step L2-latency chain). b-tile 8, grid 256, 256 threads, 2 CTAs/SM.
// Per-output FMA order unchanged (k ascending) -> identical numerics.
// act==0: src = g_Hp, sum NIC partials. act==1: BN(prev params)+GELU on src.
__global__ void __launch_bounds__(256) k_gemm(const float* __restrict__ W,
                                              const float* __restrict__ bias,
                                              const float* __restrict__ src,
                                              float* __restrict__ dst,
                                              int act) {
    extern __shared__ float gsm[];
    float* Hs   = gsm;                       // [8*HIDN] 8KB
    float* Wbuf = gsm + 8 * HIDN;            // [2][WCHUNK_F] 64KB
    unsigned long long* mbar = (unsigned long long*)(Wbuf + 2 * WCHUNK_F);  // fb0,fb1,eb0,eb1

    int b0 = blockIdx.x * 8;
    int tid = threadIdx.x;

    unsigned int fb0 = smem_u32(&mbar[0]);
    unsigned int fb1 = smem_u32(&mbar[1]);
    unsigned int eb0 = smem_u32(&mbar[2]);
    unsigned int eb1 = smem_u32(&mbar[3]);
    unsigned int wb0 = smem_u32(&Wbuf[0]);
    unsigned int wb1 = smem_u32(&Wbuf[WCHUNK_F]);

    if (tid == 0) {
        mbar_init(fb0, 1); mbar_init(fb1, 1);
        mbar_init(eb0, 8); mbar_init(eb1, 8);
    }

    for (int idx = tid; idx < 8 * HIDN; idx += 256) {
        size_t off = (size_t)b0 * HIDN + idx;
        float v;
        if (act) {
            v = src[off];
            float2 p = g_bnp[idx & (HIDN - 1)];
            v = gelu_exact(fmaf(v, p.x, p.y));
        } else {
            v = 0.f;
            #pragma unroll
            for (int p = 0; p < NIC; p++)
                v += src[(size_t)p * BATCHN * HIDN + off];
        }
        Hs[idx] = v;
    }
    __syncthreads();   // mbar init + Hs visible

    if (tid == 0) {
        mbar_expect(fb0, WCHUNK_F * 4); bulk_g2s(wb0, W, WCHUNK_F * 4, fb0);
        mbar_expect(fb1, WCHUNK_F * 4); bulk_g2s(wb1, W + WCHUNK_F, WCHUNK_F * 4, fb1);
    }

    float acc[8];
    #pragma unroll
    for (int b = 0; b < 8; b++) acc[b] = 0.f;
    int hxc = tid;

    for (int c = 0; c < NWCHUNK; c++) {
        unsigned int par = (c >> 1) & 1;
        mbar_wait((c & 1) ? fb1 : fb0, par);
        const float* Ws = Wbuf + (c & 1) * WCHUNK_F;
        const float* HsC = Hs + c * WCHUNK_K;     // k-offset within Hs rows

        #pragma unroll
        for (int k4i = 0; k4i < WCHUNK_K / 4; k4i++) {
            float w0 = Ws[(4 * k4i + 0) * HIDN + hxc];
            float w1 = Ws[(4 * k4i + 1) * HIDN + hxc];
            float w2 = Ws[(4 * k4i + 2) * HIDN + hxc];
            float w3 = Ws[(4 * k4i + 3) * HIDN + hxc];
            #pragma unroll
            for (int b = 0; b < 8; b++) {
                float4 hv = *(const float4*)&HsC[b * HIDN + 4 * k4i];
                acc[b] = fmaf(hv.x, w0, fmaf(hv.y, w1, fmaf(hv.z, w2, fmaf(hv.w, w3, acc[b]))));
            }
        }

        __syncwarp();
        if ((tid & 31) == 0) mbar_arrive((c & 1) ? eb1 : eb0);

        if (tid == 0 && c + 2 < NWCHUNK) {
            mbar_wait((c & 1) ? eb1 : eb0, par);
            unsigned int fbn = (c & 1) ? fb1 : fb0;
            mbar_expect(fbn, WCHUNK_F * 4);
            bulk_g2s((c & 1) ? wb1 : wb0, W + (size_t)(c + 2) * WCHUNK_F, WCHUNK_F * 4, fbn);
        }
    }

    float bsv = bias[hxc];
    double s1 = 0.0, s2 = 0.0;
    #pragma unroll
    for (int b = 0; b < 8; b++) {
        float y = acc[b] + bsv;
        dst[(size_t)(b0 + b) * HIDN + hxc] = y;
        s1 += (double)y;
        s2 += (double)y * (double)y;
    }
    atomicAdd(&g_sum[hxc], s1);
    atomicAdd(&g_sumsq[hxc], s2);
}

__global__ void k_bnfin(const float* __restrict__ gamma, const float* __restrict__ beta) {
    int h = threadIdx.x;
    double mean = g_sum[h] / (double)BATCHN;
    double var  = g_sumsq[h] / (double)BATCHN - mean * mean;
    float scale = gamma[h] * rsqrtf((float)var + 1e-5f);
    float shift = beta[h] - (float)mean * scale;
    g_bnp[h] = make_float2(scale, shift);
    g_sum[h] = 0.0; g_sumsq[h] = 0.0;
}

__global__ void k_final(const float* __restrict__ Wout, const float* __restrict__ bout,
                        float* __restrict__ out) {
    int b = blockIdx.x * 8 + (threadIdx.x >> 5);
    int lane = threadIdx.x & 31;
    const float* hr = g_Hb + (size_t)b * HIDN;
    float s = 0.f;
    #pragma unroll
    for (int k = lane; k < HIDN; k += 32) {
        float2 p = g_bnp[k];
        float y = gelu_exact(fmaf(hr[k], p.x, p.y));
        s = fmaf(y, Wout[k], s);
    }
    #pragma unroll
    for (int o = 16; o > 0; o >>= 1) s += __shfl_down_sync(0xffffffffu, s, o);
    if (lane == 0) out[b] = s + bout[0];
}

// ---------------- launch ----------------
extern "C" void kernel_launch(void* const* d_in, const int* in_sizes, int n_in,
                              void* d_out, int out_size) {
    const float* x     = (const float*)d_in[0];
    const float* grids = (const float*)d_in[1];
    const float* fs    = (const float*)d_in[2];
    const float* ds    = (const float*)d_in[3];
    const float* mlpW  = (const float*)d_in[4];
    const float* mlpb  = (const float*)d_in[5];
    const float* gamma = (const float*)d_in[6];
    const float* beta  = (const float*)d_in[7];
    const float* Wout  = (const float*)d_in[8];
    const float* bout  = (const float*)d_in[9];
    float* out = (float*)d_out;

    float* Ha; float* Hb; float* Hp;
    cudaGetSymbolAddress((void**)&Ha, g_Ha);
    cudaGetSymbolAddress((void**)&Hb, g_Hb);
    cudaGetSymbolAddress((void**)&Hp, g_Hp);

    cudaFuncSetAttribute(k_main, cudaFuncAttributeMaxDynamicSharedMemorySize, SMEM_MAIN);
    cudaFuncSetAttribute(k_gemm, cudaFuncAttributeMaxDynamicSharedMemorySize, SMEM_GEMM);

    k_minmax<<<IND, 256>>>(x);
    k_z<<<(BATCHN * IND + 255) / 256, 256>>>(x);
    k_sort<<<DDEPTH * IND, GRIDN>>>(grids);
    k_table<<<DDEPTH * IND, 128>>>(fs, ds);
    k_tmap<<<DDEPTH * IND, 256>>>();
    k_main<<<128, MAIN_TPB, SMEM_MAIN>>>();

    k_zstat<<<1, HIDN>>>();
    k_gemm<<<BATCHN / 8, 256, SMEM_GEMM>>>(mlpW + 0 * HIDN * HIDN, mlpb + 0 * HIDN, Hp, Hb, 0);
    k_bnfin<<<1, HIDN>>>(gamma + 0 * HIDN, beta + 0 * HIDN);
    k_gemm<<<BATCHN / 8, 256, SMEM_GEMM>>>(mlpW + 1 * HIDN * HIDN, mlpb + 1 * HIDN, Hb, Ha, 1);
    k_bnfin<<<1, HIDN>>>(gamma + 1 * HIDN, beta + 1 * HIDN);
    k_gemm<<<BATCHN / 8, 256, SMEM_GEMM>>>(mlpW + 2 * HIDN * HIDN, mlpb + 2 * HIDN, Ha, Hb, 1);
    k_bnfin<<<1, HIDN>>>(gamma + 2 * HIDN, beta + 2 * HIDN);
    k_final<<<BATCHN / 8, 256>>>(Wout, bout, out);
}